// round 3
// baseline (speedup 1.0000x reference)
#include <cuda_runtime.h>
#include <cuda_bf16.h>

// Problem constants
#define B_   4
#define S_   32
#define CIN  64
#define HID  64
#define COUT 128          // 2*HID
#define HH   32
#define WW   32
#define HWSZ 1024         // 32*32
#define FRAMES 128        // B*S
#define TOT_OUT 8388608   // B*S*HID*H*W

// Conv tiling
#define CCHUNK 8
#define OCB    8          // out-channels per block (4 packed pairs)
#define PX     8          // pixels (rows) per thread
#define CTHR   128        // threads per conv block (4 warps)

// Scratch: conv output y [frame][oc][h][w] = 128*128*1024 floats = 64 MB
__device__ float g_y[(size_t)FRAMES * COUT * HWSZ];

typedef unsigned long long u64;

__device__ __forceinline__ u64 pack2(float x) {
    u64 r;
    asm("mov.b64 %0, {%1, %2};" : "=l"(r) : "f"(x), "f"(x));
    return r;
}
__device__ __forceinline__ u64 fma2(u64 a, u64 b, u64 c) {
    u64 d;
    asm("fma.rn.f32x2 %0, %1, %2, %3;" : "=l"(d) : "l"(a), "l"(b), "l"(c));
    return d;
}
__device__ __forceinline__ void unpack2(u64 v, float& lo, float& hi) {
    asm("mov.b64 {%0, %1}, %2;" : "=f"(lo), "=f"(hi) : "l"(v));
}

__global__ __launch_bounds__(CTHR, 4) void conv_kernel(
    const float* __restrict__ x,
    const float* __restrict__ Wt,
    const float* __restrict__ bias)
{
    __shared__ __align__(16) float sIn[CCHUNK][HH + 2][WW + 2]; // 8*34*34*4 = 37 KB
    __shared__ __align__(16) float sW[CCHUNK][9][OCB];          // 8*9*8*4 = 2.3 KB

    const int oc0 = blockIdx.x * OCB;      // out-channel group
    const int f   = blockIdx.y;            // frame
    const int tid = threadIdx.x;
    const int ty  = tid >> 5;              // 0..3 (warp id)
    const int tx  = tid & 31;              // 0..31 (column)

    u64 acc[4][PX];
    #pragma unroll
    for (int j = 0; j < 4; j++)
        #pragma unroll
        for (int p = 0; p < PX; p++)
            acc[j][p] = 0ULL;

    const float* xf = x + (size_t)f * CIN * HWSZ;

    #pragma unroll 1
    for (int cc = 0; cc < CIN; cc += CCHUNK) {
        __syncthreads();
        // --- load input tile (halo): 8*34*34 = 9248 elems ---
        {
            const int NE = CCHUNK * (HH + 2) * (WW + 2);   // 9248
            #pragma unroll 1
            for (int i = tid; i < NE; i += CTHR) {
                int ci  = i / ((HH + 2) * (WW + 2));
                int rem = i - ci * ((HH + 2) * (WW + 2));
                int rr  = rem / (WW + 2);
                int col = rem - rr * (WW + 2);
                int gr  = rr - 1;
                int gc  = col - 1;
                float v = 0.f;
                if (gr >= 0 && gr < HH && gc >= 0 && gc < WW)
                    v = xf[(size_t)(cc + ci) * HWSZ + gr * WW + gc];
                sIn[ci][rr][col] = v;
            }
        }
        // --- load weights, oc-contiguous: 8*9*8 = 576 elems ---
        {
            const int NW = CCHUNK * 9 * OCB;               // 576
            #pragma unroll 1
            for (int i = tid; i < NW; i += CTHR) {
                int ci  = i / (9 * OCB);
                int rem = i - ci * (9 * OCB);
                int k   = rem / OCB;
                int o   = rem - k * OCB;
                sW[ci][k][o] = Wt[((size_t)(oc0 + o) * CIN + cc + ci) * 9 + k];
            }
        }
        __syncthreads();

        #pragma unroll 1
        for (int ci = 0; ci < CCHUNK; ci++) {
            #pragma unroll
            for (int k = 0; k < 9; k++) {
                const int dy = k / 3, dx = k % 3;
                u64 w2[4];
                #pragma unroll
                for (int j = 0; j < 4; j++)
                    w2[j] = *reinterpret_cast<const u64*>(&sW[ci][k][2 * j]); // LDS.64 broadcast
                #pragma unroll
                for (int p = 0; p < PX; p++) {
                    const int r = p * 4 + ty;              // output row
                    float xs = sIn[ci][r + dy][tx + dx];
                    u64 x2 = pack2(xs);
                    #pragma unroll
                    for (int j = 0; j < 4; j++)
                        acc[j][p] = fma2(w2[j], x2, acc[j][p]);
                }
            }
        }
    }

    // --- write y + bias ---
    #pragma unroll
    for (int j = 0; j < 4; j++) {
        const float b0 = bias[oc0 + 2 * j];
        const float b1 = bias[oc0 + 2 * j + 1];
        float* y0 = g_y + ((size_t)f * COUT + oc0 + 2 * j) * HWSZ;
        float* y1 = y0 + HWSZ;
        #pragma unroll
        for (int p = 0; p < PX; p++) {
            const int r = p * 4 + ty;
            float a0, a1;
            unpack2(acc[j][p], a0, a1);
            y0[r * WW + tx] = a0 + b0;
            y1[r * WW + tx] = a1 + b1;
        }
    }
}

__device__ __forceinline__ float softplus_f(float v) {
    return fmaxf(v, 0.f) + log1pf(expf(-fabsf(v)));
}

__global__ __launch_bounds__(256) void scan_kernel(
    const float* __restrict__ h0,
    float* __restrict__ out,
    float* __restrict__ hnext)
{
    int idx = blockIdx.x * blockDim.x + threadIdx.x;   // 0 .. B*HID*HW-1
    int hw = idx & (HWSZ - 1);
    int c  = (idx >> 10) & (HID - 1);
    int b  = idx >> 16;

    float a = 0.f;                                     // a_star running cumsum
    float L = logf(h0[((size_t)b * HID + c) * HWSZ + hw]);

    const float* gp = g_y + (size_t)b * S_ * COUT * HWSZ + (size_t)c * HWSZ + hw;
    const float* hp = gp + (size_t)HID * HWSZ;
    float* ob = out + ((size_t)b * S_ * HID) * HWSZ + (size_t)c * HWSZ + hw;

    const size_t FSTRIDE = (size_t)COUT * HWSZ;
    const size_t OSTRIDE = (size_t)HID * HWSZ;

    float last = 0.f;
    #pragma unroll 1
    for (int s = 0; s < S_; s++) {
        float gate = *gp;
        float hid  = *hp;
        gp += FSTRIDE;
        hp += FSTRIDE;

        float logc = -softplus_f(gate);                  // -softplus(gate)
        float logz = -softplus_f(-gate);                 // -softplus(-gate)
        float lth  = (hid >= 0.f) ? logf(hid + 0.5f)     // log(relu(x)+0.5)
                                  : -softplus_f(-hid);   // -softplus(-x)

        a += logc;                                       // a_star[t]
        float v = logz + lth - a;                        // log_values[t] - a_star[t]

        float mx = fmaxf(L, v);
        float mn = fminf(L, v);
        L = mx + log1pf(expf(mn - mx));

        float oh = expf(a + L);                          // exp(log_h[t])
        *ob = oh;
        ob += OSTRIDE;
        last = oh;
    }
    if (hnext)
        hnext[((size_t)b * HID + c) * HWSZ + hw] = last;
}

extern "C" void kernel_launch(void* const* d_in, const int* in_sizes, int n_in,
                              void* d_out, int out_size) {
    const float* x  = (const float*)d_in[0];
    const float* h0 = (const float*)d_in[1];
    const float* Wt = (const float*)d_in[2];
    const float* bv = (const float*)d_in[3];
    float* out = (float*)d_out;
    float* hnext = (out_size > TOT_OUT) ? out + TOT_OUT : nullptr;

    dim3 cgrid(COUT / OCB, FRAMES);              // (16, 128)
    conv_kernel<<<cgrid, CTHR>>>(x, Wt, bv);

    int nthreads = B_ * HID * HWSZ;              // 262144
    scan_kernel<<<nthreads / 256, 256>>>(h0, out, hnext);
}

// round 5
// speedup vs baseline: 2.8565x; 2.8565x over previous
#include <cuda_runtime.h>
#include <cuda_bf16.h>
#include <cstdint>

// Problem constants
#define B_   4
#define S_   32
#define CIN  64
#define HID  64
#define COUT 128
#define HH   32
#define WW   32
#define HWSZ 1024
#define FRAMES 128
#define TOT_OUT 8388608

// GEMM config
#define KTAP  192            // per-tap K = 64 cin * 3 split (bf16)
#define KPAD  200            // padded row length (400B stride -> conflict-free ldmatrix)
#define NTAPS 9
#define CTHR  256

// smem offsets (bytes)
#define XOFF   0                        // staged X': 6*32*192*2 = 73728
#define AOFF   73728                    // A panel: 128*200*2 = 51200
#define BOFF   124928                   // B panel: 128*200*2 = 51200
#define SMEM_TOTAL 176128

// Scratch
__device__ float g_y[(size_t)FRAMES * COUT * HWSZ];                       // 64 MB
__device__ __align__(16) __nv_bfloat16 g_A[NTAPS * COUT * KTAP];          // 432 KB

__device__ __forceinline__ uint32_t smem_u32(const void* p) {
    uint32_t a;
    asm("{ .reg .u64 t; cvta.to.shared.u64 t, %1; cvt.u32.u64 %0, t; }" : "=r"(a) : "l"(p));
    return a;
}
__device__ __forceinline__ void ldsm4(uint32_t& r0, uint32_t& r1, uint32_t& r2, uint32_t& r3,
                                      uint32_t addr) {
    asm volatile("ldmatrix.sync.aligned.m8n8.x4.shared.b16 {%0,%1,%2,%3}, [%4];"
                 : "=r"(r0), "=r"(r1), "=r"(r2), "=r"(r3) : "r"(addr));
}
__device__ __forceinline__ void mma16816(float* c, const uint32_t* a, const uint32_t* b) {
    asm volatile(
        "mma.sync.aligned.m16n8k16.row.col.f32.bf16.bf16.f32 "
        "{%0,%1,%2,%3}, {%4,%5,%6,%7}, {%8,%9}, {%0,%1,%2,%3};"
        : "+f"(c[0]), "+f"(c[1]), "+f"(c[2]), "+f"(c[3])
        : "r"(a[0]), "r"(a[1]), "r"(a[2]), "r"(a[3]), "r"(b[0]), "r"(b[1]));
}

// ---------------- A-prep: split W into bf16 hi/lo, layout [tap][oc][k=3c+j] ----------------
__global__ __launch_bounds__(256) void prep_kernel(const float* __restrict__ Wt) {
    int idx = blockIdx.x * blockDim.x + threadIdx.x;    // 0 .. 9*128*64-1
    if (idx >= NTAPS * COUT * CIN) return;
    int c   = idx & 63;
    int oc  = (idx >> 6) & 127;
    int tap = idx >> 13;
    float w = Wt[((size_t)oc * CIN + c) * 9 + tap];
    __nv_bfloat16 hi = __float2bfloat16(w);
    __nv_bfloat16 lo = __float2bfloat16(w - __bfloat162float(hi));
    __nv_bfloat16* base = g_A + ((size_t)tap * COUT + oc) * KTAP + 3 * c;
    base[0] = hi; base[1] = hi; base[2] = lo;
}

// ---------------- conv via mma.sync ----------------
__global__ __launch_bounds__(CTHR, 1) void conv_kernel(
    const float* __restrict__ x,
    const float* __restrict__ bias)
{
    extern __shared__ __align__(16) uint8_t smem[];
    const uint32_t sb = smem_u32(smem);
    const int tid = threadIdx.x;
    const int wid = tid >> 5;
    const int lid = tid & 31;
    const int quad = blockIdx.x;          // 0..7 -> image rows quad*4 .. quad*4+3
    const int f    = blockIdx.y;          // frame
    const int r0   = quad * 4;

    const int wm = wid & 1;               // M half (64 oc)
    const int wn = wid >> 1;              // N quarter (32 px)

    // ---- stage X': rows r0-1..r0+4 (6 rows) hi/lo/hi split, [srow*32+col][3c] ----
    {
        const float* xf = x + (size_t)f * CIN * HWSZ;
        #pragma unroll 1
        for (int i = tid; i < CIN * 6 * 32; i += CTHR) {
            int col  = i & 31;
            int srow = (i >> 5) % 6;
            int c    = i / 192;
            int grow = r0 + srow - 1;
            float v = 0.f;
            if (grow >= 0 && grow < HH)
                v = xf[(size_t)c * HWSZ + grow * WW + col];
            __nv_bfloat16 hi = __float2bfloat16(v);
            __nv_bfloat16 lo = __float2bfloat16(v - __bfloat162float(hi));
            __nv_bfloat16* dst = (__nv_bfloat16*)(smem + XOFF +
                                  ((size_t)(srow * 32 + col) * KTAP + 3 * c) * 2);
            dst[0] = hi; dst[1] = lo; dst[2] = hi;
        }
    }

    float acc[4][4][4];
    #pragma unroll
    for (int mt = 0; mt < 4; mt++)
        #pragma unroll
        for (int nt = 0; nt < 4; nt++)
            #pragma unroll
            for (int e = 0; e < 4; e++) acc[mt][nt][e] = 0.f;

    // lane-dependent ldmatrix base offsets
    const uint32_t arow = (lid & 7) + 8 * ((lid >> 3) & 1);
    const uint32_t akof = 8 * (lid >> 4);                    // elems
    const uint32_t nrow = (lid & 7) + 8 * (lid >> 4);
    const uint32_t bkof = 8 * ((lid >> 3) & 1);              // elems

    uint32_t aBase[4], bBase[2];
    #pragma unroll
    for (int mt = 0; mt < 4; mt++)
        aBase[mt] = sb + AOFF + (wm * 64 + mt * 16 + arow) * (KPAD * 2) + akof * 2;
    #pragma unroll
    for (int p = 0; p < 2; p++)
        bBase[p] = sb + BOFF + (wn * 32 + p * 16 + nrow) * (KPAD * 2) + bkof * 2;

    #pragma unroll 1
    for (int tap = 0; tap < NTAPS; tap++) {
        __syncthreads();   // prev compute done reading panels

        // ---- copy A panel: 128 x 192 bf16 = 3072 x 16B, pad rows to 200 ----
        {
            const uint4* src = (const uint4*)(g_A + (size_t)tap * COUT * KTAP);
            #pragma unroll
            for (int it = 0; it < 12; it++) {
                int i = it * CTHR + tid;             // 0..3071
                int row = i / 24;
                int j   = i - row * 24;
                *(uint4*)(smem + AOFF + row * (KPAD * 2) + j * 16) = src[i];
            }
        }
        // ---- build B panel: n px x 192 k from X' with (dy,dx) shift ----
        {
            const int dy = tap / 3, dx = tap % 3;
            #pragma unroll
            for (int it = 0; it < 12; it++) {
                int i = it * CTHR + tid;             // 0..3071
                int n = i / 24;
                int j = i - n * 24;
                int cl = n & 31, rl = n >> 5;
                int scol = cl + dx - 1;
                uint4 v = make_uint4(0, 0, 0, 0);
                if (scol >= 0 && scol < 32)
                    v = *(const uint4*)(smem + XOFF +
                          (size_t)((rl + dy) * 32 + scol) * (KTAP * 2) + j * 16);
                *(uint4*)(smem + BOFF + n * (KPAD * 2) + j * 16) = v;
            }
        }
        __syncthreads();

        // ---- compute: 12 k16-steps ----
        #pragma unroll
        for (int ks = 0; ks < 12; ks++) {
            uint32_t afr[4][4];
            #pragma unroll
            for (int mt = 0; mt < 4; mt++)
                ldsm4(afr[mt][0], afr[mt][1], afr[mt][2], afr[mt][3],
                      aBase[mt] + ks * 32);
            uint32_t bfr[2][4];
            #pragma unroll
            for (int p = 0; p < 2; p++)
                ldsm4(bfr[p][0], bfr[p][1], bfr[p][2], bfr[p][3],
                      bBase[p] + ks * 32);
            #pragma unroll
            for (int mt = 0; mt < 4; mt++)
                #pragma unroll
                for (int nt = 0; nt < 4; nt++)
                    mma16816(acc[mt][nt], afr[mt], &bfr[nt >> 1][(nt & 1) * 2]);
        }
    }

    // ---- epilogue: write y + bias ----
    {
        const int g = lid >> 2, t = lid & 3;
        #pragma unroll
        for (int mt = 0; mt < 4; mt++) {
            int oc = wm * 64 + mt * 16 + g;
            float b0 = bias[oc];
            float b1 = bias[oc + 8];
            float* y0 = g_y + ((size_t)f * COUT + oc) * HWSZ + quad * 128;
            float* y1 = y0 + 8 * HWSZ;
            #pragma unroll
            for (int nt = 0; nt < 4; nt++) {
                int px = wn * 32 + nt * 8 + 2 * t;
                float2 v0 = make_float2(acc[mt][nt][0] + b0, acc[mt][nt][1] + b0);
                float2 v1 = make_float2(acc[mt][nt][2] + b1, acc[mt][nt][3] + b1);
                *(float2*)(y0 + px) = v0;
                *(float2*)(y1 + px) = v1;
            }
        }
    }
}

// ---------------- scan ----------------
__device__ __forceinline__ float softplus_f(float v) {
    return fmaxf(v, 0.f) + log1pf(expf(-fabsf(v)));
}

__global__ __launch_bounds__(256) void scan_kernel(
    const float* __restrict__ h0,
    float* __restrict__ out,
    float* __restrict__ hnext)
{
    int idx = blockIdx.x * blockDim.x + threadIdx.x;
    int hw = idx & (HWSZ - 1);
    int c  = (idx >> 10) & (HID - 1);
    int b  = idx >> 16;

    float a = 0.f;
    float L = logf(h0[((size_t)b * HID + c) * HWSZ + hw]);

    const float* gp = g_y + (size_t)b * S_ * COUT * HWSZ + (size_t)c * HWSZ + hw;
    const float* hp = gp + (size_t)HID * HWSZ;
    float* ob = out + ((size_t)b * S_ * HID) * HWSZ + (size_t)c * HWSZ + hw;

    const size_t FSTRIDE = (size_t)COUT * HWSZ;
    const size_t OSTRIDE = (size_t)HID * HWSZ;

    float last = 0.f;
    #pragma unroll 1
    for (int s = 0; s < S_; s++) {
        float gate = *gp;
        float hid  = *hp;
        gp += FSTRIDE; hp += FSTRIDE;

        float logc = -softplus_f(gate);
        float logz = -softplus_f(-gate);
        float lth  = (hid >= 0.f) ? logf(hid + 0.5f) : -softplus_f(-hid);

        a += logc;
        float v = logz + lth - a;

        float mx = fmaxf(L, v);
        float mn = fminf(L, v);
        L = mx + log1pf(expf(mn - mx));

        float oh = expf(a + L);
        *ob = oh; ob += OSTRIDE;
        last = oh;
    }
    if (hnext)
        hnext[((size_t)b * HID + c) * HWSZ + hw] = last;
}

extern "C" void kernel_launch(void* const* d_in, const int* in_sizes, int n_in,
                              void* d_out, int out_size) {
    const float* x  = (const float*)d_in[0];
    const float* h0 = (const float*)d_in[1];
    const float* Wt = (const float*)d_in[2];
    const float* bv = (const float*)d_in[3];
    float* out = (float*)d_out;
    float* hnext = (out_size > TOT_OUT) ? out + TOT_OUT : nullptr;

    cudaFuncSetAttribute(conv_kernel, cudaFuncAttributeMaxDynamicSharedMemorySize, SMEM_TOTAL);

    prep_kernel<<<(NTAPS * COUT * CIN + 255) / 256, 256>>>(Wt);

    dim3 cgrid(8, FRAMES);                 // 1024 blocks
    conv_kernel<<<cgrid, CTHR, SMEM_TOTAL>>>(x, bv);

    scan_kernel<<<(B_ * HID * HWSZ) / 256, 256>>>(h0, out, hnext);
}

// round 6
// speedup vs baseline: 4.1428x; 1.4503x over previous
#include <cuda_runtime.h>
#include <cuda_bf16.h>
#include <cstdint>

// Problem constants
#define B_   4
#define S_   32
#define CIN  64
#define HID  64
#define COUT 128
#define HH   32
#define WW   32
#define HWSZ 1024
#define FRAMES 128
#define TOT_OUT 8388608

// GEMM config
#define KTAP  192            // per-tap K = 64 cin * 3 split (bf16)
#define KPAD  200            // padded row length (400B stride -> conflict-free ldmatrix)
#define NTAPS 9
#define CTHR  256

// smem layout (bytes)
// X' slab: 6 srows x 34 cols (zero-padded) x KPAD elems = 204 rows * 400B = 81600
#define XOFF   0
#define AOFF0  81920
#define AOFF1  133120                  // A panels: 128 rows * 400B = 51200 each
#define SMEM_TOTAL 184320

// Scratch
__device__ float g_y[(size_t)FRAMES * COUT * HWSZ];                       // 64 MB
__device__ __align__(16) __nv_bfloat16 g_A[NTAPS * COUT * KTAP];          // 432 KB

__device__ __forceinline__ uint32_t smem_u32(const void* p) {
    uint32_t a;
    asm("{ .reg .u64 t; cvta.to.shared.u64 t, %1; cvt.u32.u64 %0, t; }" : "=r"(a) : "l"(p));
    return a;
}
__device__ __forceinline__ void ldsm4(uint32_t& r0, uint32_t& r1, uint32_t& r2, uint32_t& r3,
                                      uint32_t addr) {
    asm volatile("ldmatrix.sync.aligned.m8n8.x4.shared.b16 {%0,%1,%2,%3}, [%4];"
                 : "=r"(r0), "=r"(r1), "=r"(r2), "=r"(r3) : "r"(addr));
}
__device__ __forceinline__ void mma16816(float* c, const uint32_t* a, const uint32_t* b) {
    asm volatile(
        "mma.sync.aligned.m16n8k16.row.col.f32.bf16.bf16.f32 "
        "{%0,%1,%2,%3}, {%4,%5,%6,%7}, {%8,%9}, {%0,%1,%2,%3};"
        : "+f"(c[0]), "+f"(c[1]), "+f"(c[2]), "+f"(c[3])
        : "r"(a[0]), "r"(a[1]), "r"(a[2]), "r"(a[3]), "r"(b[0]), "r"(b[1]));
}
#define CP_ASYNC16(dst, src) asm volatile("cp.async.cg.shared.global [%0], [%1], 16;" :: "r"(dst), "l"(src))
#define CP_COMMIT()          asm volatile("cp.async.commit_group;" ::: "memory")
#define CP_WAIT0()           asm volatile("cp.async.wait_group 0;" ::: "memory")

// ---------------- A-prep: split W into bf16 hi/lo, layout [tap][oc][k=3c+{hi,hi,lo}] ----------------
__global__ __launch_bounds__(256) void prep_kernel(const float* __restrict__ Wt) {
    int idx = blockIdx.x * blockDim.x + threadIdx.x;    // 0 .. 9*128*64-1
    if (idx >= NTAPS * COUT * CIN) return;
    int c   = idx & 63;
    int oc  = (idx >> 6) & 127;
    int tap = idx >> 13;
    float w = Wt[((size_t)oc * CIN + c) * 9 + tap];
    __nv_bfloat16 hi = __float2bfloat16(w);
    __nv_bfloat16 lo = __float2bfloat16(w - __bfloat162float(hi));
    __nv_bfloat16* base = g_A + ((size_t)tap * COUT + oc) * KTAP + 3 * c;
    base[0] = hi; base[1] = hi; base[2] = lo;
}

// ---------------- conv via mma.sync, direct-B ldmatrix + cp.async double-buffered A ----------------
__device__ __forceinline__ void prefetch_A(uint32_t dstbuf, int tap, int tid) {
    const char* src = (const char*)(g_A + (size_t)tap * COUT * KTAP);
    #pragma unroll
    for (int it = 0; it < 12; it++) {
        int i = it * CTHR + tid;               // 0..3071
        int row = i / 24;
        int j   = i - row * 24;
        CP_ASYNC16(dstbuf + row * (KPAD * 2) + j * 16, src + row * 384 + j * 16);
    }
}

__global__ __launch_bounds__(CTHR, 1) void conv_kernel(
    const float* __restrict__ x,
    const float* __restrict__ bias)
{
    extern __shared__ __align__(16) uint8_t smem[];
    const uint32_t sb = smem_u32(smem);
    const int tid = threadIdx.x;
    const int wid = tid >> 5;
    const int lid = tid & 31;
    const int quad = blockIdx.x;          // image rows quad*4 .. quad*4+3
    const int f    = blockIdx.y;
    const int r0   = quad * 4;

    const int wm = wid & 1;               // M half (64 oc)
    const int wn = wid >> 1;              // N quarter = image row within quad

    // prefetch tap-0 A panel
    prefetch_A(sb + AOFF0, 0, tid);
    CP_COMMIT();

    // ---- zero the dx boundary columns (col'=0 and col'=33, all 6 srows, full KPAD) ----
    {
        #pragma unroll
        for (int it = 0; it < 2; it++) {
            int i = it * CTHR + tid;                   // 0..511 (need 300)
            if (i < 12 * 25) {                          // 12 rows * 25 uint4 per row
                int r  = i / 25;                        // 0..11
                int jj = i - r * 25;
                int srow = r >> 1;
                int cp   = (r & 1) ? 33 : 0;
                *(uint4*)(smem + XOFF + ((srow * 34 + cp) * KPAD * 2) + jj * 16) =
                    make_uint4(0, 0, 0, 0);
            }
        }
    }

    // ---- stage X': 6 srows x 32 cols, hi/lo/hi split, rows padded to KPAD ----
    {
        const float* xf = x + (size_t)f * CIN * HWSZ;
        #pragma unroll 1
        for (int i = tid; i < (CIN / 2) * 6 * 32; i += CTHR) {   // 6144, c handled in pairs
            int col   = i & 31;
            int srow  = (i >> 5) % 6;
            int cpair = i / 192;                 // 0..31
            int c     = cpair * 2;
            int grow  = r0 + srow - 1;
            float v0 = 0.f, v1 = 0.f;
            if (grow >= 0 && grow < HH) {
                const float* rp = xf + (size_t)c * HWSZ + grow * WW + col;
                v0 = rp[0];
                v1 = rp[HWSZ];
            }
            __nv_bfloat16 h0 = __float2bfloat16(v0);
            __nv_bfloat16 l0 = __float2bfloat16(v0 - __bfloat162float(h0));
            __nv_bfloat16 h1 = __float2bfloat16(v1);
            __nv_bfloat16 l1 = __float2bfloat16(v1 - __bfloat162float(h1));
            // k bytes [6c .. 6c+11] = [h0,l0,h0, h1,l1,h1]
            uint32_t base = sb + XOFF + ((srow * 34 + col + 1) * KPAD + 3 * c) * 2;
            __nv_bfloat162 w0; w0.x = h0; w0.y = l0;
            __nv_bfloat162 w1; w1.x = h0; w1.y = h1;
            __nv_bfloat162 w2; w2.x = l1; w2.y = h1;
            asm volatile("st.shared.b32 [%0], %1;" :: "r"(base),     "r"(*(uint32_t*)&w0));
            asm volatile("st.shared.b32 [%0+4], %1;" :: "r"(base),   "r"(*(uint32_t*)&w1));
            asm volatile("st.shared.b32 [%0+8], %1;" :: "r"(base),   "r"(*(uint32_t*)&w2));
        }
    }

    CP_WAIT0();
    __syncthreads();

    float acc[4][4][4];
    #pragma unroll
    for (int mt = 0; mt < 4; mt++)
        #pragma unroll
        for (int nt = 0; nt < 4; nt++)
            #pragma unroll
            for (int e = 0; e < 4; e++) acc[mt][nt][e] = 0.f;

    // lane-dependent ldmatrix offsets
    const uint32_t arow = (lid & 7) + 8 * ((lid >> 3) & 1);
    const uint32_t akof = 8 * (lid >> 4);
    const uint32_t nrow = (lid & 7) + 8 * (lid >> 4);      // B row-within-16
    const uint32_t bkof = 8 * ((lid >> 3) & 1);

    const uint32_t abufs[2] = { sb + AOFF0, sb + AOFF1 };

    #pragma unroll 1
    for (int tap = 0; tap < NTAPS; tap++) {
        if (tap < NTAPS - 1) {
            prefetch_A(abufs[(tap + 1) & 1], tap + 1, tid);
            CP_COMMIT();
        }
        const int dy = tap / 3, dx = tap % 3;
        const uint32_t abuf = abufs[tap & 1];

        uint32_t aBase[4];
        #pragma unroll
        for (int mt = 0; mt < 4; mt++)
            aBase[mt] = abuf + (wm * 64 + mt * 16 + arow) * (KPAD * 2) + akof * 2;
        // B direct from X': pixel n = wn*32 + p*16 + nrow -> X'[(wn+dy)][p*16+nrow + dx]
        uint32_t bBase[2];
        #pragma unroll
        for (int p = 0; p < 2; p++)
            bBase[p] = sb + XOFF +
                       (((wn + dy) * 34 + p * 16 + nrow + dx) * KPAD + bkof) * 2;

        #pragma unroll
        for (int ks = 0; ks < 12; ks++) {
            uint32_t afr[4][4];
            #pragma unroll
            for (int mt = 0; mt < 4; mt++)
                ldsm4(afr[mt][0], afr[mt][1], afr[mt][2], afr[mt][3], aBase[mt] + ks * 32);
            uint32_t bfr[2][4];
            #pragma unroll
            for (int p = 0; p < 2; p++)
                ldsm4(bfr[p][0], bfr[p][1], bfr[p][2], bfr[p][3], bBase[p] + ks * 32);
            #pragma unroll
            for (int mt = 0; mt < 4; mt++)
                #pragma unroll
                for (int nt = 0; nt < 4; nt++)
                    mma16816(acc[mt][nt], afr[mt], &bfr[nt >> 1][(nt & 1) * 2]);
        }

        if (tap < NTAPS - 1) {
            CP_WAIT0();
            __syncthreads();
        }
    }

    // ---- epilogue: write y + bias ----
    {
        const int g = lid >> 2, t = lid & 3;
        #pragma unroll
        for (int mt = 0; mt < 4; mt++) {
            int oc = wm * 64 + mt * 16 + g;
            float b0 = bias[oc];
            float b1 = bias[oc + 8];
            float* y0 = g_y + ((size_t)f * COUT + oc) * HWSZ + quad * 128;
            float* y1 = y0 + 8 * HWSZ;
            #pragma unroll
            for (int nt = 0; nt < 4; nt++) {
                int px = wn * 32 + nt * 8 + 2 * t;
                *(float2*)(y0 + px) = make_float2(acc[mt][nt][0] + b0, acc[mt][nt][1] + b0);
                *(float2*)(y1 + px) = make_float2(acc[mt][nt][2] + b1, acc[mt][nt][3] + b1);
            }
        }
    }
}

// ---------------- scan (fast-math transcendentals) ----------------
__global__ __launch_bounds__(256) void scan_kernel(
    const float* __restrict__ h0,
    float* __restrict__ out,
    float* __restrict__ hnext)
{
    int idx = blockIdx.x * blockDim.x + threadIdx.x;
    int hw = idx & (HWSZ - 1);
    int c  = (idx >> 10) & (HID - 1);
    int b  = idx >> 16;

    float a = 0.f;
    float L = __logf(h0[((size_t)b * HID + c) * HWSZ + hw]);

    const float* gp = g_y + (size_t)b * S_ * COUT * HWSZ + (size_t)c * HWSZ + hw;
    const float* hp = gp + (size_t)HID * HWSZ;
    float* ob = out + ((size_t)b * S_ * HID) * HWSZ + (size_t)c * HWSZ + hw;

    const size_t FSTRIDE = (size_t)COUT * HWSZ;
    const size_t OSTRIDE = (size_t)HID * HWSZ;

    float last = 0.f;
    #pragma unroll 4
    for (int s = 0; s < S_; s++) {
        float gate = *gp;
        float hid  = *hp;
        gp += FSTRIDE; hp += FSTRIDE;

        // softplus(g) = max(g,0)+log1p(exp(-|g|)); share exp(-|g|) for +/-g
        float eg  = __expf(-fabsf(gate));
        float lg  = __logf(1.f + eg);
        float logc = -(fmaxf(gate, 0.f) + lg);     // -softplus(gate)
        float logz = -(fmaxf(-gate, 0.f) + lg);    // -softplus(-gate)

        float lth;
        if (hid >= 0.f) lth = __logf(hid + 0.5f);
        else            lth = hid - __logf(1.f + __expf(hid));   // -softplus(-hid)

        a += logc;
        float v = logz + lth - a;

        float mx = fmaxf(L, v);
        float mn = fminf(L, v);
        L = mx + __logf(1.f + __expf(mn - mx));

        float oh = __expf(a + L);
        *ob = oh; ob += OSTRIDE;
        last = oh;
    }
    if (hnext)
        hnext[((size_t)b * HID + c) * HWSZ + hw] = last;
}

extern "C" void kernel_launch(void* const* d_in, const int* in_sizes, int n_in,
                              void* d_out, int out_size) {
    const float* x  = (const float*)d_in[0];
    const float* h0 = (const float*)d_in[1];
    const float* Wt = (const float*)d_in[2];
    const float* bv = (const float*)d_in[3];
    float* out = (float*)d_out;
    float* hnext = (out_size > TOT_OUT) ? out + TOT_OUT : nullptr;

    cudaFuncSetAttribute(conv_kernel, cudaFuncAttributeMaxDynamicSharedMemorySize, SMEM_TOTAL);

    prep_kernel<<<(NTAPS * COUT * CIN + 255) / 256, 256>>>(Wt);

    dim3 cgrid(8, FRAMES);                 // 1024 blocks
    conv_kernel<<<cgrid, CTHR, SMEM_TOTAL>>>(x, bv);

    scan_kernel<<<(B_ * HID * HWSZ) / 256, 256>>>(h0, out, hnext);
}

// round 7
// speedup vs baseline: 4.8854x; 1.1793x over previous
#include <cuda_runtime.h>
#include <cuda_bf16.h>
#include <cstdint>

// Problem constants
#define B_   4
#define S_   32
#define CIN  64
#define HID  64
#define COUT 128
#define HH   32
#define WW   32
#define HWSZ 1024
#define FRAMES 128
#define TOT_OUT 8388608

// GEMM config
#define KTAP  192            // per-tap K = 64 cin * 3 split (bf16)
#define KPAD  200            // padded row length (400B stride -> conflict-free ldmatrix)
#define NTAPS 9
#define CTHR  512            // 16 warps
#define RPB   8              // image rows per block
#define NSROW 10             // staged source rows (RPB + 2 halo)
#define SLOTS 33             // 1 zero slot + 32 data cols per srow (wrap trick)
#define XROWS (NSROW * SLOTS + 1)   // 331 rows (incl. tail zero row)

// smem layout (bytes)
#define XOFF   0                           // X' slab: 331 * 400 = 132400
#define AOFF   132400                      // A panel: 128 * 400 = 51200
#define SMEM_TOTAL 183600

// Scratch
__device__ float g_y[(size_t)FRAMES * COUT * HWSZ];                       // 64 MB
__device__ __align__(16) __nv_bfloat16 g_A[NTAPS * COUT * KTAP];          // 432 KB

__device__ __forceinline__ uint32_t smem_u32(const void* p) {
    uint32_t a;
    asm("{ .reg .u64 t; cvta.to.shared.u64 t, %1; cvt.u32.u64 %0, t; }" : "=r"(a) : "l"(p));
    return a;
}
__device__ __forceinline__ void ldsm4(uint32_t& r0, uint32_t& r1, uint32_t& r2, uint32_t& r3,
                                      uint32_t addr) {
    asm volatile("ldmatrix.sync.aligned.m8n8.x4.shared.b16 {%0,%1,%2,%3}, [%4];"
                 : "=r"(r0), "=r"(r1), "=r"(r2), "=r"(r3) : "r"(addr));
}
__device__ __forceinline__ void mma16816(float* c, const uint32_t* a, const uint32_t* b) {
    asm volatile(
        "mma.sync.aligned.m16n8k16.row.col.f32.bf16.bf16.f32 "
        "{%0,%1,%2,%3}, {%4,%5,%6,%7}, {%8,%9}, {%0,%1,%2,%3};"
        : "+f"(c[0]), "+f"(c[1]), "+f"(c[2]), "+f"(c[3])
        : "r"(a[0]), "r"(a[1]), "r"(a[2]), "r"(a[3]), "r"(b[0]), "r"(b[1]));
}
#define CP_ASYNC16(dst, src) asm volatile("cp.async.cg.shared.global [%0], [%1], 16;" :: "r"(dst), "l"(src))
#define CP_COMMIT()          asm volatile("cp.async.commit_group;" ::: "memory")
#define CP_WAIT0()           asm volatile("cp.async.wait_group 0;" ::: "memory")
#define CP_WAIT1()           asm volatile("cp.async.wait_group 1;" ::: "memory")

// ---------------- A-prep: split W into bf16 hi/lo, layout [tap][oc][k=3c+{hi,hi,lo}] ----------------
__global__ __launch_bounds__(256) void prep_kernel(const float* __restrict__ Wt) {
    int idx = blockIdx.x * blockDim.x + threadIdx.x;    // 0 .. 9*128*64-1
    if (idx >= NTAPS * COUT * CIN) return;
    int c   = idx & 63;
    int oc  = (idx >> 6) & 127;
    int tap = idx >> 13;
    float w = Wt[((size_t)oc * CIN + c) * 9 + tap];
    __nv_bfloat16 hi = __float2bfloat16(w);
    __nv_bfloat16 lo = __float2bfloat16(w - __bfloat162float(hi));
    __nv_bfloat16* base = g_A + ((size_t)tap * COUT + oc) * KTAP + 3 * c;
    base[0] = hi; base[1] = hi; base[2] = lo;
}

// prefetch one K-half (96 elems = 192B per row) of a tap's A panel
__device__ __forceinline__ void prefetch_A_half(uint32_t abuf, int tap, int half, int tid) {
    const char* src = (const char*)(g_A + (size_t)tap * COUT * KTAP) + half * 192;
    uint32_t dst = abuf + half * 192;
    #pragma unroll
    for (int it = 0; it < 3; it++) {
        int i = it * CTHR + tid;               // 0..1535
        int row = i / 12;
        int j   = i - row * 12;
        CP_ASYNC16(dst + row * (KPAD * 2) + j * 16, src + row * 384 + j * 16);
    }
}

__global__ __launch_bounds__(CTHR, 1) void conv_kernel(
    const float* __restrict__ x,
    const float* __restrict__ bias)
{
    extern __shared__ __align__(16) uint8_t smem[];
    const uint32_t sb = smem_u32(smem);
    const int tid = threadIdx.x;
    const int wid = tid >> 5;
    const int lid = tid & 31;
    const int rg  = blockIdx.x;           // row group: image rows rg*8 .. rg*8+7
    const int f   = blockIdx.y;
    const int r0  = rg * RPB;

    const int wm = wid & 1;               // M half (64 oc)
    const int wn = wid >> 1;              // image row within block (0..7)

    // prefetch tap-0 A halves
    prefetch_A_half(sb + AOFF, 0, 0, tid);
    CP_COMMIT();
    prefetch_A_half(sb + AOFF, 0, 1, tid);
    CP_COMMIT();

    // ---- zero slots: row srow*33 for srow 0..9, plus tail row 330 ----
    {
        int i = tid;                       // need 11*25 = 275 <= 512
        if (i < 11 * 25) {
            int r_idx = i / 25;
            int jj    = i - r_idx * 25;
            int row   = (r_idx < NSROW) ? r_idx * SLOTS : NSROW * SLOTS;
            *(uint4*)(smem + XOFF + row * (KPAD * 2) + jj * 16) = make_uint4(0, 0, 0, 0);
        }
    }

    // ---- stage X': 10 srows x 32 cols, hi/lo/hi split, c in pairs ----
    {
        const float* xf = x + (size_t)f * CIN * HWSZ;
        #pragma unroll 1
        for (int i = tid; i < (CIN / 2) * NSROW * 32; i += CTHR) {   // 10240
            int col   = i & 31;
            int srow  = (i >> 5) % NSROW;
            int cpair = i / (NSROW * 32);
            int c     = cpair * 2;
            int grow  = r0 + srow - 1;
            float v0 = 0.f, v1 = 0.f;
            if (grow >= 0 && grow < HH) {
                const float* rp = xf + (size_t)c * HWSZ + grow * WW + col;
                v0 = rp[0];
                v1 = rp[HWSZ];
            }
            __nv_bfloat16 h0 = __float2bfloat16(v0);
            __nv_bfloat16 l0 = __float2bfloat16(v0 - __bfloat162float(h0));
            __nv_bfloat16 h1 = __float2bfloat16(v1);
            __nv_bfloat16 l1 = __float2bfloat16(v1 - __bfloat162float(h1));
            int row = srow * SLOTS + col + 1;
            uint32_t base = sb + XOFF + (uint32_t)(row * (KPAD * 2) + 12 * cpair);
            __nv_bfloat162 w0; w0.x = h0; w0.y = l0;
            __nv_bfloat162 w1; w1.x = h0; w1.y = h1;
            __nv_bfloat162 w2; w2.x = l1; w2.y = h1;
            asm volatile("st.shared.b32 [%0], %1;"   :: "r"(base), "r"(*(uint32_t*)&w0));
            asm volatile("st.shared.b32 [%0+4], %1;" :: "r"(base), "r"(*(uint32_t*)&w1));
            asm volatile("st.shared.b32 [%0+8], %1;" :: "r"(base), "r"(*(uint32_t*)&w2));
        }
    }

    CP_WAIT0();
    __syncthreads();

    float acc[4][4][4];
    #pragma unroll
    for (int mt = 0; mt < 4; mt++)
        #pragma unroll
        for (int nt = 0; nt < 4; nt++)
            #pragma unroll
            for (int e = 0; e < 4; e++) acc[mt][nt][e] = 0.f;

    // lane-dependent ldmatrix offsets
    const uint32_t arow = (lid & 7) + 8 * ((lid >> 3) & 1);
    const uint32_t akof = 8 * (lid >> 4);
    const uint32_t nrow = (lid & 7) + 8 * (lid >> 4);      // B row-within-16
    const uint32_t bkof = 8 * ((lid >> 3) & 1);

    const uint32_t abuf = sb + AOFF;
    uint32_t aBase[4];
    #pragma unroll
    for (int mt = 0; mt < 4; mt++)
        aBase[mt] = abuf + (wm * 64 + mt * 16 + arow) * (KPAD * 2) + akof * 2;

    #pragma unroll 1
    for (int tap = 0; tap < NTAPS; tap++) {
        const int dy = tap / 3, dx = tap % 3;
        // B direct from X': px = p*16+nrow in image row r0+wn -> slab row (wn+dy)*33 + px + dx
        uint32_t bBase[2];
        #pragma unroll
        for (int p = 0; p < 2; p++)
            bBase[p] = sb + XOFF +
                       ((uint32_t)((wn + dy) * SLOTS + p * 16 + nrow + dx) * KPAD + bkof) * 2;

        #pragma unroll
        for (int half = 0; half < 2; half++) {
            #pragma unroll
            for (int k6 = 0; k6 < 6; k6++) {
                const int ks = half * 6 + k6;
                uint32_t afr[4][4];
                #pragma unroll
                for (int mt = 0; mt < 4; mt++)
                    ldsm4(afr[mt][0], afr[mt][1], afr[mt][2], afr[mt][3], aBase[mt] + ks * 32);
                uint32_t bfr[2][4];
                #pragma unroll
                for (int p = 0; p < 2; p++)
                    ldsm4(bfr[p][0], bfr[p][1], bfr[p][2], bfr[p][3], bBase[p] + ks * 32);
                #pragma unroll
                for (int mt = 0; mt < 4; mt++)
                    #pragma unroll
                    for (int nt = 0; nt < 4; nt++)
                        mma16816(acc[mt][nt], afr[mt], &bfr[nt >> 1][(nt & 1) * 2]);
            }
            __syncthreads();                    // all warps done reading this half
            if (tap < NTAPS - 1) {
                prefetch_A_half(abuf, tap + 1, half, tid);   // overwrite this half
                CP_COMMIT();
                CP_WAIT1();    // half==0: ensures tap's h1 arrived; half==1: ensures (tap+1)'s h0 arrived
            }
            __syncthreads();
        }
    }

    // ---- epilogue: write y + bias ----
    {
        const int g = lid >> 2, t = lid & 3;
        #pragma unroll
        for (int mt = 0; mt < 4; mt++) {
            int oc = wm * 64 + mt * 16 + g;
            float b0 = bias[oc];
            float b1 = bias[oc + 8];
            float* y0 = g_y + ((size_t)f * COUT + oc) * HWSZ + (r0 + wn) * WW;
            float* y1 = y0 + 8 * HWSZ;
            #pragma unroll
            for (int nt = 0; nt < 4; nt++) {
                int px = nt * 8 + 2 * t;
                *(float2*)(y0 + px) = make_float2(acc[mt][nt][0] + b0, acc[mt][nt][1] + b0);
                *(float2*)(y1 + px) = make_float2(acc[mt][nt][2] + b1, acc[mt][nt][3] + b1);
            }
        }
    }
}

// ---------------- scan (fast-math transcendentals) ----------------
__global__ __launch_bounds__(256) void scan_kernel(
    const float* __restrict__ h0,
    float* __restrict__ out,
    float* __restrict__ hnext)
{
    int idx = blockIdx.x * blockDim.x + threadIdx.x;
    int hw = idx & (HWSZ - 1);
    int c  = (idx >> 10) & (HID - 1);
    int b  = idx >> 16;

    float a = 0.f;
    float L = __logf(h0[((size_t)b * HID + c) * HWSZ + hw]);

    const float* gp = g_y + (size_t)b * S_ * COUT * HWSZ + (size_t)c * HWSZ + hw;
    const float* hp = gp + (size_t)HID * HWSZ;
    float* ob = out + ((size_t)b * S_ * HID) * HWSZ + (size_t)c * HWSZ + hw;

    const size_t FSTRIDE = (size_t)COUT * HWSZ;
    const size_t OSTRIDE = (size_t)HID * HWSZ;

    float last = 0.f;
    #pragma unroll 4
    for (int s = 0; s < S_; s++) {
        float gate = *gp;
        float hid  = *hp;
        gp += FSTRIDE; hp += FSTRIDE;

        float eg  = __expf(-fabsf(gate));
        float lg  = __logf(1.f + eg);
        float logc = -(fmaxf(gate, 0.f) + lg);     // -softplus(gate)
        float logz = -(fmaxf(-gate, 0.f) + lg);    // -softplus(-gate)

        float lth;
        if (hid >= 0.f) lth = __logf(hid + 0.5f);
        else            lth = hid - __logf(1.f + __expf(hid));   // -softplus(-hid)

        a += logc;
        float v = logz + lth - a;

        float mx = fmaxf(L, v);
        float mn = fminf(L, v);
        L = mx + __logf(1.f + __expf(mn - mx));

        float oh = __expf(a + L);
        *ob = oh; ob += OSTRIDE;
        last = oh;
    }
    if (hnext)
        hnext[((size_t)b * HID + c) * HWSZ + hw] = last;
}

extern "C" void kernel_launch(void* const* d_in, const int* in_sizes, int n_in,
                              void* d_out, int out_size) {
    const float* x  = (const float*)d_in[0];
    const float* h0 = (const float*)d_in[1];
    const float* Wt = (const float*)d_in[2];
    const float* bv = (const float*)d_in[3];
    float* out = (float*)d_out;
    float* hnext = (out_size > TOT_OUT) ? out + TOT_OUT : nullptr;

    cudaFuncSetAttribute(conv_kernel, cudaFuncAttributeMaxDynamicSharedMemorySize, SMEM_TOTAL);

    prep_kernel<<<(NTAPS * COUT * CIN + 255) / 256, 256>>>(Wt);

    dim3 cgrid(HH / RPB, FRAMES);          // (4, 128) = 512 blocks
    conv_kernel<<<cgrid, CTHR, SMEM_TOTAL>>>(x, bv);

    scan_kernel<<<(B_ * HID * HWSZ) / 256, 256>>>(h0, out, hnext);
}

// round 8
// speedup vs baseline: 6.5595x; 1.3427x over previous
#include <cuda_runtime.h>
#include <cuda_fp16.h>
#include <cstdint>

// Problem constants
#define B_   4
#define S_   32
#define CIN  64
#define HID  64
#define COUT 128
#define HH   32
#define WW   32
#define HWSZ 1024
#define FRAMES 128
#define TOT_OUT 8388608

// GEMM config (fp16 2-term split: K per tap = 64 ch * 2)
#define KTAP  128
#define KPADE 136            // padded row length in elems (272B stride, 17x16B -> conflict-free)
#define ROWB  272            // row stride bytes
#define NTAPS 9
#define CTHR  512            // 16 warps
#define RPB   8              // image rows per block
#define NSROW 10             // staged source rows (RPB + 2 halo)
#define SLOTS 33             // 1 zero slot + 32 data cols per srow (wrap trick)

// smem layout (bytes)
#define XOFF   0                           // X' slab: 331 rows * 272B = 90032
#define AOFF0  90032                       // A panel buf0: 128 * 272 = 34816
#define AOFF1  124848                      // A panel buf1
#define SMEM_TOTAL 159664

// Scratch
__device__ float g_y[(size_t)FRAMES * COUT * HWSZ];               // 64 MB
__device__ __align__(16) __half g_A[NTAPS * COUT * KTAP];         // 288 KB

__device__ __forceinline__ uint32_t smem_u32(const void* p) {
    uint32_t a;
    asm("{ .reg .u64 t; cvta.to.shared.u64 t, %1; cvt.u32.u64 %0, t; }" : "=r"(a) : "l"(p));
    return a;
}
__device__ __forceinline__ void ldsm4(uint32_t& r0, uint32_t& r1, uint32_t& r2, uint32_t& r3,
                                      uint32_t addr) {
    asm volatile("ldmatrix.sync.aligned.m8n8.x4.shared.b16 {%0,%1,%2,%3}, [%4];"
                 : "=r"(r0), "=r"(r1), "=r"(r2), "=r"(r3) : "r"(addr));
}
__device__ __forceinline__ void mma16816(float* c, const uint32_t* a, const uint32_t* b) {
    asm volatile(
        "mma.sync.aligned.m16n8k16.row.col.f32.f16.f16.f32 "
        "{%0,%1,%2,%3}, {%4,%5,%6,%7}, {%8,%9}, {%0,%1,%2,%3};"
        : "+f"(c[0]), "+f"(c[1]), "+f"(c[2]), "+f"(c[3])
        : "r"(a[0]), "r"(a[1]), "r"(a[2]), "r"(a[3]), "r"(b[0]), "r"(b[1]));
}
#define CP_ASYNC16(dst, src) asm volatile("cp.async.cg.shared.global [%0], [%1], 16;" :: "r"(dst), "l"(src))
#define CP_COMMIT()          asm volatile("cp.async.commit_group;" ::: "memory")
#define CP_WAIT0()           asm volatile("cp.async.wait_group 0;" ::: "memory")

// ---------------- A-prep: split W into fp16 hi/lo, layout [tap][oc][k=2c+{hi,lo}] ----------------
__global__ __launch_bounds__(256) void prep_kernel(const float* __restrict__ Wt) {
    int idx = blockIdx.x * blockDim.x + threadIdx.x;    // 0 .. 9*128*64-1
    if (idx >= NTAPS * COUT * CIN) return;
    int c   = idx & 63;
    int oc  = (idx >> 6) & 127;
    int tap = idx >> 13;
    float w = Wt[((size_t)oc * CIN + c) * 9 + tap];
    __half hi = __float2half_rn(w);
    __half lo = __float2half_rn(w - __half2float(hi));
    __half* base = g_A + ((size_t)tap * COUT + oc) * KTAP + 2 * c;
    base[0] = hi; base[1] = lo;
}

// prefetch one whole tap A panel (128 rows x 256B -> 2048 x 16B), 4 chunks/thread
__device__ __forceinline__ void prefetch_A(uint32_t abuf, int tap, int tid) {
    const char* src = (const char*)(g_A + (size_t)tap * COUT * KTAP);
    #pragma unroll
    for (int it = 0; it < 4; it++) {
        int i = it * CTHR + tid;               // 0..2047
        int row = i >> 4;
        int j   = i & 15;
        CP_ASYNC16(abuf + row * ROWB + j * 16, src + i * 16);
    }
}

__global__ __launch_bounds__(CTHR, 1) void conv_kernel(
    const float* __restrict__ x,
    const float* __restrict__ bias)
{
    extern __shared__ __align__(16) uint8_t smem[];
    const uint32_t sb = smem_u32(smem);
    const int tid = threadIdx.x;
    const int wid = tid >> 5;
    const int lid = tid & 31;
    const int rg  = blockIdx.x;           // image rows rg*8 .. rg*8+7
    const int f   = blockIdx.y;
    const int r0  = rg * RPB;

    const int wm = wid & 1;               // M half (64 oc)
    const int wn = wid >> 1;              // image row within block (0..7)

    prefetch_A(sb + AOFF0, 0, tid);
    CP_COMMIT();

    // ---- zero slots: rows srow*33 (srow 0..9) + tail row 330 : 11 rows x 17 uint4 ----
    if (tid < 11 * 17) {
        int r_idx = tid / 17;
        int jj    = tid - r_idx * 17;
        int row   = (r_idx < NSROW) ? r_idx * SLOTS : NSROW * SLOTS;
        *(uint4*)(smem + XOFF + row * ROWB + jj * 16) = make_uint4(0, 0, 0, 0);
    }

    // ---- stage X': 10 srows x 32 cols, fp16 duplicated (xhi,xhi), c in pairs ----
    {
        const float* xf = x + (size_t)f * CIN * HWSZ;
        #pragma unroll 1
        for (int i = tid; i < (CIN / 2) * NSROW * 32; i += CTHR) {   // 10240 -> 20 iters
            int col   = i & 31;
            int srow  = (i >> 5) % NSROW;
            int cpair = i / (NSROW * 32);
            int c     = cpair * 2;
            int grow  = r0 + srow - 1;
            float v0 = 0.f, v1 = 0.f;
            if (grow >= 0 && grow < HH) {
                const float* rp = xf + (size_t)c * HWSZ + grow * WW + col;
                v0 = rp[0];
                v1 = rp[HWSZ];
            }
            __half h0 = __float2half_rn(v0);
            __half h1 = __float2half_rn(v1);
            __half2 p0; p0.x = h0; p0.y = h0;
            __half2 p1; p1.x = h1; p1.y = h1;
            int row = srow * SLOTS + col + 1;
            uint32_t base = sb + XOFF + (uint32_t)(row * ROWB + 8 * cpair);
            asm volatile("st.shared.v2.b32 [%0], {%1, %2};"
                         :: "r"(base), "r"(*(uint32_t*)&p0), "r"(*(uint32_t*)&p1));
        }
    }

    CP_WAIT0();
    __syncthreads();

    float acc[4][4][4];
    #pragma unroll
    for (int mt = 0; mt < 4; mt++)
        #pragma unroll
        for (int nt = 0; nt < 4; nt++)
            #pragma unroll
            for (int e = 0; e < 4; e++) acc[mt][nt][e] = 0.f;

    // lane-dependent ldmatrix offsets (identical mapping to bf16 m16n8k16)
    const uint32_t arow = (lid & 7) + 8 * ((lid >> 3) & 1);
    const uint32_t akof = 8 * (lid >> 4);                  // elems
    const uint32_t nrow = (lid & 7) + 8 * (lid >> 4);      // B row-within-16
    const uint32_t bkof = 8 * ((lid >> 3) & 1);            // elems

    const uint32_t abufs[2] = { sb + AOFF0, sb + AOFF1 };

    #pragma unroll 1
    for (int tap = 0; tap < NTAPS; tap++) {
        if (tap < NTAPS - 1) {
            prefetch_A(abufs[(tap + 1) & 1], tap + 1, tid);   // other buffer, free since last sync
            CP_COMMIT();
        }
        const int dy = tap / 3, dx = tap % 3;
        const uint32_t abuf = abufs[tap & 1];

        uint32_t aBase[4];
        #pragma unroll
        for (int mt = 0; mt < 4; mt++)
            aBase[mt] = abuf + (wm * 64 + mt * 16 + arow) * ROWB + akof * 2;
        uint32_t bBase[2];
        #pragma unroll
        for (int p = 0; p < 2; p++)
            bBase[p] = sb + XOFF +
                       (uint32_t)((wn + dy) * SLOTS + p * 16 + nrow + dx) * ROWB + bkof * 2;

        #pragma unroll
        for (int ks = 0; ks < 8; ks++) {       // 8 k16-steps (KTAP=128)
            uint32_t afr[4][4];
            #pragma unroll
            for (int mt = 0; mt < 4; mt++)
                ldsm4(afr[mt][0], afr[mt][1], afr[mt][2], afr[mt][3], aBase[mt] + ks * 32);
            uint32_t bfr[2][4];
            #pragma unroll
            for (int p = 0; p < 2; p++)
                ldsm4(bfr[p][0], bfr[p][1], bfr[p][2], bfr[p][3], bBase[p] + ks * 32);
            #pragma unroll
            for (int mt = 0; mt < 4; mt++)
                #pragma unroll
                for (int nt = 0; nt < 4; nt++)
                    mma16816(acc[mt][nt], afr[mt], &bfr[nt >> 1][(nt & 1) * 2]);
        }

        if (tap < NTAPS - 1) {
            CP_WAIT0();        // next tap's panel arrived
            __syncthreads();   // all warps done reading old buffer + see new data
        }
    }

    // ---- epilogue: write y + bias ----
    {
        const int g = lid >> 2, t = lid & 3;
        #pragma unroll
        for (int mt = 0; mt < 4; mt++) {
            int oc = wm * 64 + mt * 16 + g;
            float b0 = bias[oc];
            float b1 = bias[oc + 8];
            float* y0 = g_y + ((size_t)f * COUT + oc) * HWSZ + (r0 + wn) * WW;
            float* y1 = y0 + 8 * HWSZ;
            #pragma unroll
            for (int nt = 0; nt < 4; nt++) {
                int px = nt * 8 + 2 * t;
                *(float2*)(y0 + px) = make_float2(acc[mt][nt][0] + b0, acc[mt][nt][1] + b0);
                *(float2*)(y1 + px) = make_float2(acc[mt][nt][2] + b1, acc[mt][nt][3] + b1);
            }
        }
    }
}

// ---------------- scan (fast-math transcendentals) ----------------
__global__ __launch_bounds__(256) void scan_kernel(
    const float* __restrict__ h0,
    float* __restrict__ out,
    float* __restrict__ hnext)
{
    int idx = blockIdx.x * blockDim.x + threadIdx.x;
    int hw = idx & (HWSZ - 1);
    int c  = (idx >> 10) & (HID - 1);
    int b  = idx >> 16;

    float a = 0.f;
    float L = __logf(h0[((size_t)b * HID + c) * HWSZ + hw]);

    const float* gp = g_y + (size_t)b * S_ * COUT * HWSZ + (size_t)c * HWSZ + hw;
    const float* hp = gp + (size_t)HID * HWSZ;
    float* ob = out + ((size_t)b * S_ * HID) * HWSZ + (size_t)c * HWSZ + hw;

    const size_t FSTRIDE = (size_t)COUT * HWSZ;
    const size_t OSTRIDE = (size_t)HID * HWSZ;

    float last = 0.f;
    #pragma unroll 4
    for (int s = 0; s < S_; s++) {
        float gate = *gp;
        float hid  = *hp;
        gp += FSTRIDE; hp += FSTRIDE;

        float eg  = __expf(-fabsf(gate));
        float lg  = __logf(1.f + eg);
        float logc = -(fmaxf(gate, 0.f) + lg);     // -softplus(gate)
        float logz = -(fmaxf(-gate, 0.f) + lg);    // -softplus(-gate)

        float lth;
        if (hid >= 0.f) lth = __logf(hid + 0.5f);
        else            lth = hid - __logf(1.f + __expf(hid));   // -softplus(-hid)

        a += logc;
        float v = logz + lth - a;

        float mx = fmaxf(L, v);
        float mn = fminf(L, v);
        L = mx + __logf(1.f + __expf(mn - mx));

        float oh = __expf(a + L);
        *ob = oh; ob += OSTRIDE;
        last = oh;
    }
    if (hnext)
        hnext[((size_t)b * HID + c) * HWSZ + hw] = last;
}

extern "C" void kernel_launch(void* const* d_in, const int* in_sizes, int n_in,
                              void* d_out, int out_size) {
    const float* x  = (const float*)d_in[0];
    const float* h0 = (const float*)d_in[1];
    const float* Wt = (const float*)d_in[2];
    const float* bv = (const float*)d_in[3];
    float* out = (float*)d_out;
    float* hnext = (out_size > TOT_OUT) ? out + TOT_OUT : nullptr;

    cudaFuncSetAttribute(conv_kernel, cudaFuncAttributeMaxDynamicSharedMemorySize, SMEM_TOTAL);

    prep_kernel<<<(NTAPS * COUT * CIN + 255) / 256, 256>>>(Wt);

    dim3 cgrid(HH / RPB, FRAMES);          // (4, 128) = 512 blocks
    conv_kernel<<<cgrid, CTHR, SMEM_TOTAL>>>(x, bv);

    scan_kernel<<<(B_ * HID * HWSZ) / 256, 256>>>(h0, out, hnext);
}

// round 9
// speedup vs baseline: 8.5288x; 1.3002x over previous
#include <cuda_runtime.h>
#include <cuda_fp16.h>
#include <cstdint>

// Problem constants
#define B_   4
#define S_   32
#define CIN  64
#define HID  64
#define COUT 128
#define HH   32
#define WW   32
#define HWSZ 1024
#define FRAMES 128
#define TOT_OUT 8388608

// GEMM config (pure fp16: K per tap = 64 channels)
#define KTAP  64
#define ROWB  144            // row stride bytes (9 x 16B -> ldmatrix conflict-free)
#define NTAPS 9
#define CTHR  512            // 16 warps
#define RPB   8              // image rows per block
#define NSROW 10             // staged source rows (RPB + 2 halo)
#define SLOTS 33             // 1 zero slot + 32 data cols per srow (wrap trick)
#define XROWS (NSROW * SLOTS + 1)   // 331 rows

// smem layout (bytes)
#define XOFF   0                           // X' slab: 331 * 144 = 47664
#define AOFF0  47664                       // A panel buf0: 128 * 144 = 18432
#define AOFF1  66096                       // A panel buf1
#define SMEM_TOTAL 84528

// Scratch
__device__ float g_y[(size_t)FRAMES * COUT * HWSZ];               // 64 MB
__device__ __align__(16) __half g_A[NTAPS * COUT * KTAP];         // 144 KB

__device__ __forceinline__ uint32_t smem_u32(const void* p) {
    uint32_t a;
    asm("{ .reg .u64 t; cvta.to.shared.u64 t, %1; cvt.u32.u64 %0, t; }" : "=r"(a) : "l"(p));
    return a;
}
__device__ __forceinline__ void ldsm4(uint32_t& r0, uint32_t& r1, uint32_t& r2, uint32_t& r3,
                                      uint32_t addr) {
    asm volatile("ldmatrix.sync.aligned.m8n8.x4.shared.b16 {%0,%1,%2,%3}, [%4];"
                 : "=r"(r0), "=r"(r1), "=r"(r2), "=r"(r3) : "r"(addr));
}
__device__ __forceinline__ void mma16816(float* c, const uint32_t* a, const uint32_t* b) {
    asm volatile(
        "mma.sync.aligned.m16n8k16.row.col.f32.f16.f16.f32 "
        "{%0,%1,%2,%3}, {%4,%5,%6,%7}, {%8,%9}, {%0,%1,%2,%3};"
        : "+f"(c[0]), "+f"(c[1]), "+f"(c[2]), "+f"(c[3])
        : "r"(a[0]), "r"(a[1]), "r"(a[2]), "r"(a[3]), "r"(b[0]), "r"(b[1]));
}
#define CP_ASYNC16(dst, src) asm volatile("cp.async.cg.shared.global [%0], [%1], 16;" :: "r"(dst), "l"(src))
#define CP_COMMIT()          asm volatile("cp.async.commit_group;" ::: "memory")
#define CP_WAIT0()           asm volatile("cp.async.wait_group 0;" ::: "memory")

// ---------------- A-prep: W -> fp16, layout [tap][oc][k=c] ----------------
__global__ __launch_bounds__(256) void prep_kernel(const float* __restrict__ Wt) {
    int idx = blockIdx.x * blockDim.x + threadIdx.x;    // 0 .. 9*128*64-1
    if (idx >= NTAPS * COUT * CIN) return;
    int c   = idx & 63;
    int oc  = (idx >> 6) & 127;
    int tap = idx >> 13;
    float w = Wt[((size_t)oc * CIN + c) * 9 + tap];
    g_A[((size_t)tap * COUT + oc) * KTAP + c] = __float2half_rn(w);
}

// prefetch one tap's A panel: 128 rows x 128B = 1024 x 16B, 2 chunks/thread
__device__ __forceinline__ void prefetch_A(uint32_t abuf, int tap, int tid) {
    const char* src = (const char*)(g_A + (size_t)tap * COUT * KTAP);
    #pragma unroll
    for (int it = 0; it < 2; it++) {
        int i = it * CTHR + tid;               // 0..1023
        int row = i >> 3;
        int j   = i & 7;
        CP_ASYNC16(abuf + row * ROWB + j * 16, src + i * 16);
    }
}

__global__ __launch_bounds__(CTHR, 1) void conv_kernel(
    const float* __restrict__ x,
    const float* __restrict__ bias)
{
    extern __shared__ __align__(16) uint8_t smem[];
    const uint32_t sb = smem_u32(smem);
    const int tid = threadIdx.x;
    const int wid = tid >> 5;
    const int lid = tid & 31;
    const int rg  = blockIdx.x;           // image rows rg*8 .. rg*8+7
    const int f   = blockIdx.y;
    const int r0  = rg * RPB;

    const int wm = wid & 1;               // M half (64 oc)
    const int wn = wid >> 1;              // image row within block (0..7)

    prefetch_A(sb + AOFF0, 0, tid);
    CP_COMMIT();

    // ---- zero slots: rows srow*33 (srow 0..9) + tail row 330 : 11 rows x 9 uint4 ----
    if (tid < 11 * 9) {
        int r_idx = tid / 9;
        int jj    = tid - r_idx * 9;
        int row   = (r_idx < NSROW) ? r_idx * SLOTS : NSROW * SLOTS;
        *(uint4*)(smem + XOFF + row * ROWB + jj * 16) = make_uint4(0, 0, 0, 0);
    }

    // ---- stage X': 10 srows x 32 cols x 32 cpairs, fp16 (c, c+1) packed in one b32 ----
    {
        const float* xf = x + (size_t)f * CIN * HWSZ;
        #pragma unroll 1
        for (int i = tid; i < (CIN / 2) * NSROW * 32; i += CTHR) {   // 10240 -> 20 iters
            int col   = i & 31;
            int srow  = (i >> 5) % NSROW;
            int cpair = i / (NSROW * 32);
            int c     = cpair * 2;
            int grow  = r0 + srow - 1;
            float v0 = 0.f, v1 = 0.f;
            if (grow >= 0 && grow < HH) {
                const float* rp = xf + (size_t)c * HWSZ + grow * WW + col;
                v0 = rp[0];
                v1 = rp[HWSZ];
            }
            __half2 pk;
            pk.x = __float2half_rn(v0);
            pk.y = __float2half_rn(v1);
            int row = srow * SLOTS + col + 1;
            uint32_t addr = sb + XOFF + (uint32_t)(row * ROWB + 4 * cpair);
            asm volatile("st.shared.b32 [%0], %1;" :: "r"(addr), "r"(*(uint32_t*)&pk));
        }
    }

    CP_WAIT0();
    __syncthreads();

    float acc[4][4][4];
    #pragma unroll
    for (int mt = 0; mt < 4; mt++)
        #pragma unroll
        for (int nt = 0; nt < 4; nt++)
            #pragma unroll
            for (int e = 0; e < 4; e++) acc[mt][nt][e] = 0.f;

    // lane-dependent ldmatrix offsets
    const uint32_t arow = (lid & 7) + 8 * ((lid >> 3) & 1);
    const uint32_t akof = 8 * (lid >> 4);                  // elems
    const uint32_t nrow = (lid & 7) + 8 * (lid >> 4);      // B row-within-16
    const uint32_t bkof = 8 * ((lid >> 3) & 1);            // elems

    const uint32_t abufs[2] = { sb + AOFF0, sb + AOFF1 };

    #pragma unroll 1
    for (int tap = 0; tap < NTAPS; tap++) {
        if (tap < NTAPS - 1) {
            prefetch_A(abufs[(tap + 1) & 1], tap + 1, tid);
            CP_COMMIT();
        }
        const int dy = tap / 3, dx = tap % 3;
        const uint32_t abuf = abufs[tap & 1];

        uint32_t aBase[4];
        #pragma unroll
        for (int mt = 0; mt < 4; mt++)
            aBase[mt] = abuf + (wm * 64 + mt * 16 + arow) * ROWB + akof * 2;
        uint32_t bBase[2];
        #pragma unroll
        for (int p = 0; p < 2; p++)
            bBase[p] = sb + XOFF +
                       (uint32_t)((wn + dy) * SLOTS + p * 16 + nrow + dx) * ROWB + bkof * 2;

        #pragma unroll
        for (int ks = 0; ks < 4; ks++) {       // 4 k16-steps (KTAP=64)
            uint32_t afr[4][4];
            #pragma unroll
            for (int mt = 0; mt < 4; mt++)
                ldsm4(afr[mt][0], afr[mt][1], afr[mt][2], afr[mt][3], aBase[mt] + ks * 32);
            uint32_t bfr[2][4];
            #pragma unroll
            for (int p = 0; p < 2; p++)
                ldsm4(bfr[p][0], bfr[p][1], bfr[p][2], bfr[p][3], bBase[p] + ks * 32);
            #pragma unroll
            for (int mt = 0; mt < 4; mt++)
                #pragma unroll
                for (int nt = 0; nt < 4; nt++)
                    mma16816(acc[mt][nt], afr[mt], &bfr[nt >> 1][(nt & 1) * 2]);
        }

        if (tap < NTAPS - 1) {
            CP_WAIT0();
            __syncthreads();
        }
    }

    // ---- epilogue: write y + bias ----
    {
        const int g = lid >> 2, t = lid & 3;
        #pragma unroll
        for (int mt = 0; mt < 4; mt++) {
            int oc = wm * 64 + mt * 16 + g;
            float b0 = bias[oc];
            float b1 = bias[oc + 8];
            float* y0 = g_y + ((size_t)f * COUT + oc) * HWSZ + (r0 + wn) * WW;
            float* y1 = y0 + 8 * HWSZ;
            #pragma unroll
            for (int nt = 0; nt < 4; nt++) {
                int px = nt * 8 + 2 * t;
                *(float2*)(y0 + px) = make_float2(acc[mt][nt][0] + b0, acc[mt][nt][1] + b0);
                *(float2*)(y1 + px) = make_float2(acc[mt][nt][2] + b1, acc[mt][nt][3] + b1);
            }
        }
    }
}

// ---------------- scan (fast-math transcendentals) ----------------
__global__ __launch_bounds__(256) void scan_kernel(
    const float* __restrict__ h0,
    float* __restrict__ out,
    float* __restrict__ hnext)
{
    int idx = blockIdx.x * blockDim.x + threadIdx.x;
    int hw = idx & (HWSZ - 1);
    int c  = (idx >> 10) & (HID - 1);
    int b  = idx >> 16;

    float a = 0.f;
    float L = __logf(h0[((size_t)b * HID + c) * HWSZ + hw]);

    const float* gp = g_y + (size_t)b * S_ * COUT * HWSZ + (size_t)c * HWSZ + hw;
    const float* hp = gp + (size_t)HID * HWSZ;
    float* ob = out + ((size_t)b * S_ * HID) * HWSZ + (size_t)c * HWSZ + hw;

    const size_t FSTRIDE = (size_t)COUT * HWSZ;
    const size_t OSTRIDE = (size_t)HID * HWSZ;

    float last = 0.f;
    #pragma unroll 4
    for (int s = 0; s < S_; s++) {
        float gate = *gp;
        float hid  = *hp;
        gp += FSTRIDE; hp += FSTRIDE;

        float eg  = __expf(-fabsf(gate));
        float lg  = __logf(1.f + eg);
        float logc = -(fmaxf(gate, 0.f) + lg);     // -softplus(gate)
        float logz = -(fmaxf(-gate, 0.f) + lg);    // -softplus(-gate)

        float lth;
        if (hid >= 0.f) lth = __logf(hid + 0.5f);
        else            lth = hid - __logf(1.f + __expf(hid));   // -softplus(-hid)

        a += logc;
        float v = logz + lth - a;

        float mx = fmaxf(L, v);
        float mn = fminf(L, v);
        L = mx + __logf(1.f + __expf(mn - mx));

        float oh = __expf(a + L);
        *ob = oh; ob += OSTRIDE;
        last = oh;
    }
    if (hnext)
        hnext[((size_t)b * HID + c) * HWSZ + hw] = last;
}

extern "C" void kernel_launch(void* const* d_in, const int* in_sizes, int n_in,
                              void* d_out, int out_size) {
    const float* x  = (const float*)d_in[0];
    const float* h0 = (const float*)d_in[1];
    const float* Wt = (const float*)d_in[2];
    const float* bv = (const float*)d_in[3];
    float* out = (float*)d_out;
    float* hnext = (out_size > TOT_OUT) ? out + TOT_OUT : nullptr;

    cudaFuncSetAttribute(conv_kernel, cudaFuncAttributeMaxDynamicSharedMemorySize, SMEM_TOTAL);

    prep_kernel<<<(NTAPS * COUT * CIN + 255) / 256, 256>>>(Wt);

    dim3 cgrid(HH / RPB, FRAMES);          // (4, 128) = 512 blocks
    conv_kernel<<<cgrid, CTHR, SMEM_TOTAL>>>(x, bv);

    scan_kernel<<<(B_ * HID * HWSZ) / 256, 256>>>(h0, out, hnext);
}

// round 10
// speedup vs baseline: 8.6898x; 1.0189x over previous
#include <cuda_runtime.h>
#include <cuda_fp16.h>
#include <cstdint>

// Problem constants
#define B_   4
#define S_   32
#define CIN  64
#define HID  64
#define COUT 128
#define HH   32
#define WW   32
#define HWSZ 1024
#define FRAMES 128
#define TOT_OUT 8388608

// GEMM config (pure fp16: K per tap = 64 channels)
#define KTAP  64
#define ROWB  144            // row stride bytes (9 x 16B -> ldmatrix conflict-free)
#define NTAPS 9
#define CTHR  256            // 8 warps
#define RPB   4              // image rows per block
#define NSROW 6              // staged source rows (RPB + 2 halo)
#define SLOTS 33             // 1 zero slot + 32 data cols per srow (wrap trick)
#define XROWS (NSROW * SLOTS + 1)   // 199 rows

// smem layout (bytes)
#define XOFF   0                           // X' slab: 199 * 144 = 28656
#define AOFF0  28656                       // A panel buf0: 128 * 144 = 18432
#define AOFF1  47088                       // A panel buf1
#define SMEM_TOTAL 65520

// Scratch
__device__ float g_y[(size_t)FRAMES * COUT * HWSZ];               // 64 MB
__device__ __align__(16) __half g_A[NTAPS * COUT * KTAP];         // 144 KB

__device__ __forceinline__ uint32_t smem_u32(const void* p) {
    uint32_t a;
    asm("{ .reg .u64 t; cvta.to.shared.u64 t, %1; cvt.u32.u64 %0, t; }" : "=r"(a) : "l"(p));
    return a;
}
__device__ __forceinline__ void ldsm4(uint32_t& r0, uint32_t& r1, uint32_t& r2, uint32_t& r3,
                                      uint32_t addr) {
    asm volatile("ldmatrix.sync.aligned.m8n8.x4.shared.b16 {%0,%1,%2,%3}, [%4];"
                 : "=r"(r0), "=r"(r1), "=r"(r2), "=r"(r3) : "r"(addr));
}
__device__ __forceinline__ void mma16816(float* c, const uint32_t* a, const uint32_t* b) {
    asm volatile(
        "mma.sync.aligned.m16n8k16.row.col.f32.f16.f16.f32 "
        "{%0,%1,%2,%3}, {%4,%5,%6,%7}, {%8,%9}, {%0,%1,%2,%3};"
        : "+f"(c[0]), "+f"(c[1]), "+f"(c[2]), "+f"(c[3])
        : "r"(a[0]), "r"(a[1]), "r"(a[2]), "r"(a[3]), "r"(b[0]), "r"(b[1]));
}
#define CP_ASYNC16(dst, src) asm volatile("cp.async.cg.shared.global [%0], [%1], 16;" :: "r"(dst), "l"(src))
#define CP_COMMIT()          asm volatile("cp.async.commit_group;" ::: "memory")
#define CP_WAIT0()           asm volatile("cp.async.wait_group 0;" ::: "memory")

// ---------------- A-prep: W -> fp16, layout [tap][oc][k=c] ----------------
__global__ __launch_bounds__(256) void prep_kernel(const float* __restrict__ Wt) {
    int idx = blockIdx.x * blockDim.x + threadIdx.x;    // 0 .. 9*128*64-1
    if (idx >= NTAPS * COUT * CIN) return;
    int c   = idx & 63;
    int oc  = (idx >> 6) & 127;
    int tap = idx >> 13;
    float w = Wt[((size_t)oc * CIN + c) * 9 + tap];
    g_A[((size_t)tap * COUT + oc) * KTAP + c] = __float2half_rn(w);
}

// prefetch one tap's A panel: 128 rows x 128B = 1024 x 16B, 4 chunks/thread
__device__ __forceinline__ void prefetch_A(uint32_t abuf, int tap, int tid) {
    const char* src = (const char*)(g_A + (size_t)tap * COUT * KTAP);
    #pragma unroll
    for (int it = 0; it < 4; it++) {
        int i = it * CTHR + tid;               // 0..1023
        int row = i >> 3;
        int j   = i & 7;
        CP_ASYNC16(abuf + row * ROWB + j * 16, src + i * 16);
    }
}

__global__ __launch_bounds__(CTHR, 2) void conv_kernel(
    const float* __restrict__ x,
    const float* __restrict__ bias)
{
    extern __shared__ __align__(16) uint8_t smem[];
    const uint32_t sb = smem_u32(smem);
    const int tid = threadIdx.x;
    const int wid = tid >> 5;
    const int lid = tid & 31;
    const int rg  = blockIdx.x;           // image rows rg*4 .. rg*4+3
    const int f   = blockIdx.y;
    const int r0  = rg * RPB;

    const int wm = wid & 1;               // M half (64 oc)
    const int wn = wid >> 1;              // image row within block (0..3)

    prefetch_A(sb + AOFF0, 0, tid);
    CP_COMMIT();

    // ---- zero slots: rows srow*33 (srow 0..5) + tail row 198 : 7 rows x 9 uint4 ----
    if (tid < 7 * 9) {
        int r_idx = tid / 9;
        int jj    = tid - r_idx * 9;
        int row   = (r_idx < NSROW) ? r_idx * SLOTS : NSROW * SLOTS;
        *(uint4*)(smem + XOFF + row * ROWB + jj * 16) = make_uint4(0, 0, 0, 0);
    }

    // ---- stage X': 6 srows x 32 cols x 32 cpairs, fp16 (c, c+1) packed in one b32 ----
    {
        const float* xf = x + (size_t)f * CIN * HWSZ;
        #pragma unroll 1
        for (int i = tid; i < (CIN / 2) * NSROW * 32; i += CTHR) {   // 6144 -> 24 iters
            int col   = i & 31;
            int srow  = (i >> 5) % NSROW;
            int cpair = i / (NSROW * 32);
            int c     = cpair * 2;
            int grow  = r0 + srow - 1;
            float v0 = 0.f, v1 = 0.f;
            if (grow >= 0 && grow < HH) {
                const float* rp = xf + (size_t)c * HWSZ + grow * WW + col;
                v0 = rp[0];
                v1 = rp[HWSZ];
            }
            __half2 pk;
            pk.x = __float2half_rn(v0);
            pk.y = __float2half_rn(v1);
            int row = srow * SLOTS + col + 1;
            uint32_t addr = sb + XOFF + (uint32_t)(row * ROWB + 4 * cpair);
            asm volatile("st.shared.b32 [%0], %1;" :: "r"(addr), "r"(*(uint32_t*)&pk));
        }
    }

    CP_WAIT0();
    __syncthreads();

    float acc[4][4][4];
    #pragma unroll
    for (int mt = 0; mt < 4; mt++)
        #pragma unroll
        for (int nt = 0; nt < 4; nt++)
            #pragma unroll
            for (int e = 0; e < 4; e++) acc[mt][nt][e] = 0.f;

    // lane-dependent ldmatrix offsets
    const uint32_t arow = (lid & 7) + 8 * ((lid >> 3) & 1);
    const uint32_t akof = 8 * (lid >> 4);                  // elems
    const uint32_t nrow = (lid & 7) + 8 * (lid >> 4);      // B row-within-16
    const uint32_t bkof = 8 * ((lid >> 3) & 1);            // elems

    const uint32_t abufs[2] = { sb + AOFF0, sb + AOFF1 };

    #pragma unroll 1
    for (int tap = 0; tap < NTAPS; tap++) {
        if (tap < NTAPS - 1) {
            prefetch_A(abufs[(tap + 1) & 1], tap + 1, tid);
            CP_COMMIT();
        }
        const int dy = tap / 3, dx = tap % 3;
        const uint32_t abuf = abufs[tap & 1];

        uint32_t aBase[4];
        #pragma unroll
        for (int mt = 0; mt < 4; mt++)
            aBase[mt] = abuf + (wm * 64 + mt * 16 + arow) * ROWB + akof * 2;
        uint32_t bBase[2];
        #pragma unroll
        for (int p = 0; p < 2; p++)
            bBase[p] = sb + XOFF +
                       (uint32_t)((wn + dy) * SLOTS + p * 16 + nrow + dx) * ROWB + bkof * 2;

        #pragma unroll
        for (int ks = 0; ks < 4; ks++) {       // 4 k16-steps (KTAP=64)
            uint32_t afr[4][4];
            #pragma unroll
            for (int mt = 0; mt < 4; mt++)
                ldsm4(afr[mt][0], afr[mt][1], afr[mt][2], afr[mt][3], aBase[mt] + ks * 32);
            uint32_t bfr[2][4];
            #pragma unroll
            for (int p = 0; p < 2; p++)
                ldsm4(bfr[p][0], bfr[p][1], bfr[p][2], bfr[p][3], bBase[p] + ks * 32);
            #pragma unroll
            for (int mt = 0; mt < 4; mt++)
                #pragma unroll
                for (int nt = 0; nt < 4; nt++)
                    mma16816(acc[mt][nt], afr[mt], &bfr[nt >> 1][(nt & 1) * 2]);
        }

        if (tap < NTAPS - 1) {
            CP_WAIT0();
            __syncthreads();
        }
    }

    // ---- epilogue: write y + bias ----
    {
        const int g = lid >> 2, t = lid & 3;
        #pragma unroll
        for (int mt = 0; mt < 4; mt++) {
            int oc = wm * 64 + mt * 16 + g;
            float b0 = bias[oc];
            float b1 = bias[oc + 8];
            float* y0 = g_y + ((size_t)f * COUT + oc) * HWSZ + (r0 + wn) * WW;
            float* y1 = y0 + 8 * HWSZ;
            #pragma unroll
            for (int nt = 0; nt < 4; nt++) {
                int px = nt * 8 + 2 * t;
                *(float2*)(y0 + px) = make_float2(acc[mt][nt][0] + b0, acc[mt][nt][1] + b0);
                *(float2*)(y1 + px) = make_float2(acc[mt][nt][2] + b1, acc[mt][nt][3] + b1);
            }
        }
    }
}

// ---------------- scan: 2 independent chains per thread for ILP ----------------
__global__ __launch_bounds__(256) void scan_kernel(
    const float* __restrict__ h0,
    float* __restrict__ out,
    float* __restrict__ hnext)
{
    // block covers 512 consecutive elements; thread handles e0 and e0+256
    int e0 = blockIdx.x * 512 + threadIdx.x;
    int hw0 = e0 & (HWSZ - 1);            // e1 differs only in hw bits (+256)
    int c   = (e0 >> 10) & (HID - 1);
    int b   = e0 >> 16;

    size_t base_h = ((size_t)b * HID + c) * HWSZ + hw0;
    float a0 = 0.f, a1 = 0.f;
    float L0 = __logf(h0[base_h]);
    float L1 = __logf(h0[base_h + 256]);

    const float* gp = g_y + (size_t)b * S_ * COUT * HWSZ + (size_t)c * HWSZ + hw0;
    const float* hp = gp + (size_t)HID * HWSZ;
    float* ob = out + ((size_t)b * S_ * HID) * HWSZ + (size_t)c * HWSZ + hw0;

    const size_t FSTRIDE = (size_t)COUT * HWSZ;
    const size_t OSTRIDE = (size_t)HID * HWSZ;

    float last0 = 0.f, last1 = 0.f;
    #pragma unroll 4
    for (int s = 0; s < S_; s++) {
        float gate0 = gp[0],   gate1 = gp[256];
        float hid0  = hp[0],   hid1  = hp[256];
        gp += FSTRIDE; hp += FSTRIDE;

        // chain 0
        float eg0  = __expf(-fabsf(gate0));
        float lg0  = __logf(1.f + eg0);
        float logc0 = -(fmaxf(gate0, 0.f) + lg0);
        float logz0 = -(fmaxf(-gate0, 0.f) + lg0);
        float lth0 = (hid0 >= 0.f) ? __logf(hid0 + 0.5f)
                                   : hid0 - __logf(1.f + __expf(hid0));
        a0 += logc0;
        float v0 = logz0 + lth0 - a0;
        float mx0 = fmaxf(L0, v0), mn0 = fminf(L0, v0);
        L0 = mx0 + __logf(1.f + __expf(mn0 - mx0));
        float oh0 = __expf(a0 + L0);

        // chain 1
        float eg1  = __expf(-fabsf(gate1));
        float lg1  = __logf(1.f + eg1);
        float logc1 = -(fmaxf(gate1, 0.f) + lg1);
        float logz1 = -(fmaxf(-gate1, 0.f) + lg1);
        float lth1 = (hid1 >= 0.f) ? __logf(hid1 + 0.5f)
                                   : hid1 - __logf(1.f + __expf(hid1));
        a1 += logc1;
        float v1 = logz1 + lth1 - a1;
        float mx1 = fmaxf(L1, v1), mn1 = fminf(L1, v1);
        L1 = mx1 + __logf(1.f + __expf(mn1 - mx1));
        float oh1 = __expf(a1 + L1);

        ob[0]   = oh0;
        ob[256] = oh1;
        ob += OSTRIDE;
        last0 = oh0; last1 = oh1;
    }
    if (hnext) {
        hnext[base_h]       = last0;
        hnext[base_h + 256] = last1;
    }
}

extern "C" void kernel_launch(void* const* d_in, const int* in_sizes, int n_in,
                              void* d_out, int out_size) {
    const float* x  = (const float*)d_in[0];
    const float* h0 = (const float*)d_in[1];
    const float* Wt = (const float*)d_in[2];
    const float* bv = (const float*)d_in[3];
    float* out = (float*)d_out;
    float* hnext = (out_size > TOT_OUT) ? out + TOT_OUT : nullptr;

    cudaFuncSetAttribute(conv_kernel, cudaFuncAttributeMaxDynamicSharedMemorySize, SMEM_TOTAL);

    prep_kernel<<<(NTAPS * COUT * CIN + 255) / 256, 256>>>(Wt);

    dim3 cgrid(HH / RPB, FRAMES);          // (8, 128) = 1024 blocks
    conv_kernel<<<cgrid, CTHR, SMEM_TOTAL>>>(x, bv);

    scan_kernel<<<(B_ * HID * HWSZ) / 512, 256>>>(h0, out, hnext);
}